// round 10
// baseline (speedup 1.0000x reference)
#include <cuda_runtime.h>
#include <cuda_bf16.h>
#include <cstdint>
#include <math.h>

#define BATCH 8
#define S1V   2048
#define S2V   2048
#define HV    1024

typedef __nv_bfloat16 bf16;

// ----------------------------------------------------------------------------
// Scratch (device globals)
// ----------------------------------------------------------------------------
__device__ bf16 g_wh [(size_t)HV * HV];            // W hi/lo
__device__ bf16 g_wl [(size_t)HV * HV];
__device__ bf16 g_qph[(size_t)BATCH * S1V * HV];   // qproj hi/lo
__device__ bf16 g_qpl[(size_t)BATCH * S1V * HV];
__device__ bf16 g_vth[(size_t)BATCH * HV * S1V];   // valueT hi/lo [B,H,S1]
__device__ bf16 g_vtl[(size_t)BATCH * HV * S1V];
__device__ float g_scores[(size_t)BATCH * S2V * S1V];  // masked logits [B,S2,S1]

#define NEG_INF __int_as_float(0xff800000)

// ----------------------------------------------------------------------------
// PTX helpers (plain sm_80+ features only)
// ----------------------------------------------------------------------------
__device__ __forceinline__ uint32_t smem_u32(const void* p) {
    uint32_t a;
    asm("{ .reg .u64 t; cvta.to.shared.u64 t, %1; cvt.u32.u64 %0, t; }" : "=r"(a) : "l"(p));
    return a;
}
__device__ __forceinline__ void cp_async16(uint32_t dst, const void* src) {
    asm volatile("cp.async.cg.shared.global [%0], [%1], 16;" :: "r"(dst), "l"(src));
}
#define CP_COMMIT() asm volatile("cp.async.commit_group;" ::: "memory")
#define CP_WAIT0()  asm volatile("cp.async.wait_group 0;" ::: "memory")

__device__ __forceinline__ void ldsm4(uint32_t r[4], uint32_t addr) {
    asm volatile("ldmatrix.sync.aligned.m8n8.x4.shared.b16 {%0,%1,%2,%3}, [%4];"
                 : "=r"(r[0]), "=r"(r[1]), "=r"(r[2]), "=r"(r[3]) : "r"(addr));
}
__device__ __forceinline__ void mma16816(float c[4], const uint32_t a[4],
                                         const uint32_t b0, const uint32_t b1) {
    asm volatile("mma.sync.aligned.m16n8k16.row.col.f32.bf16.bf16.f32 "
                 "{%0,%1,%2,%3}, {%4,%5,%6,%7}, {%8,%9}, {%0,%1,%2,%3};"
                 : "+f"(c[0]), "+f"(c[1]), "+f"(c[2]), "+f"(c[3])
                 : "r"(a[0]), "r"(a[1]), "r"(a[2]), "r"(a[3]), "r"(b0), "r"(b1));
}

#define SWZ(o) ((o) ^ (((o) >> 3) & 0x70))

__device__ __forceinline__ uint32_t pack2(float x0, float x1) {
    bf16 h0 = __float2bfloat16(x0), h1 = __float2bfloat16(x1);
    return (uint32_t)__bfloat16_as_ushort(h0) | ((uint32_t)__bfloat16_as_ushort(h1) << 16);
}

// ----------------------------------------------------------------------------
// Split-bf16 NT GEMM on mma.sync:  C[M,N] = A_fp32[M,K] @ (Bh+Bl)[N,K]^T
// A is fp32 in GMEM; each chunk is cp.async'd raw, then split into hi/lo bf16
// swizzled tiles in smem (same byte traffic as pre-split hi+lo).
// Block tile 128x128, K-chunk 64, 2-stage pipeline, 8 warps (2M x 4N),
// warp tile 64x32, 3 split passes (hi*hi + hi*lo + lo*hi) in fp32 accum.
// EPI: 0 = fp32 store (optional mask -> -inf); 1 = +bias, hi/lo split store.
// ----------------------------------------------------------------------------
#define TILE_M 128
#define TILE_N 128
#define TILE_K 64
#define OFF_AF 0          // 32KB fp32 A staging
#define OFF_AH 32768      // 16KB A hi tile (SW128)
#define OFF_AL 49152      // 16KB A lo tile
#define OFF_BH 65536      // 16KB B hi tile
#define OFF_BL 81920      // 16KB B lo tile
#define STAGE_BYTES 98304
#define SMEM_BYTES  (2 * STAGE_BYTES)

__device__ __forceinline__ void load_stage(
    uint32_t sbase,
    const float* A, const bf16* Bh, const bf16* Bl,
    long long m0, long long n0, long long ldA, long long ldB, int k0, int tid)
{
    // A fp32: 128 rows x 256B, plain row-major staging
#pragma unroll
    for (int i = tid; i < 2048; i += 256) {
        int r = i >> 4, c = i & 15;
        cp_async16(sbase + OFF_AF + r * 256 + c * 16, A + (m0 + r) * ldA + k0 + c * 4);
    }
    // B bf16 hi/lo: 128 rows x 128B each, SW128 swizzled
#pragma unroll
    for (int i = tid; i < 1024; i += 256) {
        int r = i >> 3, c = i & 7;
        uint32_t sw = SWZ(r * 128 + c * 16);
        long long goff = (n0 + r) * ldB + k0 + c * 8;
        cp_async16(sbase + OFF_BH + sw, Bh + goff);
        cp_async16(sbase + OFF_BL + sw, Bl + goff);
    }
}

__device__ __forceinline__ void convertA(char* stage, int tid)
{
    // 8192 fp32 -> hi/lo bf16 swizzled tiles; 8 float4 per thread
#pragma unroll
    for (int i = 0; i < 8; i++) {
        int j = tid + i * 256;
        int row = j >> 4;
        int c4  = (j & 15) * 4;            // first float col of this quad
        float4 v = *(const float4*)(stage + OFF_AF + (size_t)j * 16);
        bf16 h0 = __float2bfloat16(v.x), h1 = __float2bfloat16(v.y);
        bf16 h2 = __float2bfloat16(v.z), h3 = __float2bfloat16(v.w);
        float r0 = v.x - __bfloat162float(h0), r1 = v.y - __bfloat162float(h1);
        float r2 = v.z - __bfloat162float(h2), r3 = v.w - __bfloat162float(h3);
        uint2 hp, lp;
        hp.x = (uint32_t)__bfloat16_as_ushort(h0) | ((uint32_t)__bfloat16_as_ushort(h1) << 16);
        hp.y = (uint32_t)__bfloat16_as_ushort(h2) | ((uint32_t)__bfloat16_as_ushort(h3) << 16);
        lp.x = pack2(r0, r1);
        lp.y = pack2(r2, r3);
        uint32_t sw = SWZ((uint32_t)(row * 128 + c4 * 2));
        *(uint2*)(stage + OFF_AH + sw) = hp;
        *(uint2*)(stage + OFF_AL + sw) = lp;
    }
}

template <int EPI, int MASK>
__global__ __launch_bounds__(256) void mma_gemm(
    const float* __restrict__ A,
    const bf16* __restrict__ Bh, const bf16* __restrict__ Bl,
    const float* __restrict__ bias,
    float* __restrict__ Cf, bf16* __restrict__ Ch, bf16* __restrict__ Cl,
    const int* __restrict__ maskp,
    int K, int N,
    long long ldA, long long ldB,
    long long sA, long long sB, long long sC, long long sMask)
{
    extern __shared__ char smem[];
    const uint32_t sb = smem_u32(smem);

    const int tid  = threadIdx.x;
    const int wid  = tid >> 5;
    const int lane = tid & 31;
    const int wm = wid & 1;      // 2 M-groups of 64
    const int wn = wid >> 1;     // 4 N-groups of 32

    const long long bz = blockIdx.z;
    A  += bz * sA;
    Bh += bz * sB;  Bl += bz * sB;
    const int* mb = MASK ? (maskp + bz * sMask) : nullptr;
    const long long m0 = (long long)blockIdx.y * TILE_M;
    const long long n0 = (long long)blockIdx.x * TILE_N;

    // ldmatrix lane addressing
    const int g  = lane >> 3;
    const int lr = lane & 7;
    const int rowA = wm * 64 + (g & 1) * 8 + lr;
    const int kbA  = (g >> 1) * 16;
    const int rowB = wn * 32 + (g >> 1) * 8 + lr;
    const int kbB  = (g & 1) * 16;

    float acc[4][4][4];
#pragma unroll
    for (int i = 0; i < 4; i++)
#pragma unroll
        for (int j = 0; j < 4; j++)
#pragma unroll
            for (int r = 0; r < 4; r++) acc[i][j][r] = 0.f;

    const int NKC = K / TILE_K;

    // prologue: stage 0 load + convert
    load_stage(sb, A, Bh, Bl, m0, n0, ldA, ldB, 0, tid);
    CP_COMMIT();
    CP_WAIT0();
    __syncthreads();
    convertA(smem, tid);
    __syncthreads();

    for (int kc = 0; kc < NKC; ++kc) {
        const int cur = kc & 1;
        const uint32_t sbase = sb + cur * STAGE_BYTES;
        char* curp = smem + (size_t)cur * STAGE_BYTES;
        (void)curp;

        if (kc + 1 < NKC) {
            load_stage(sb + (cur ^ 1) * STAGE_BYTES, A, Bh, Bl,
                       m0, n0, ldA, ldB, (kc + 1) * TILE_K, tid);
            CP_COMMIT();
        }

        // ---- MMAs on current stage ----
#pragma unroll
        for (int ks = 0; ks < 4; ++ks) {
            uint32_t ah[4][4], al[4][4];
#pragma unroll
            for (int i = 0; i < 4; i++) {
                uint32_t off = SWZ((uint32_t)((rowA + i * 16) * 128 + ks * 32 + kbA));
                ldsm4(ah[i], sbase + OFF_AH + off);
                ldsm4(al[i], sbase + OFF_AL + off);
            }
            uint32_t bh[2][4], bl[2][4];
#pragma unroll
            for (int jj = 0; jj < 2; jj++) {
                uint32_t off = SWZ((uint32_t)((rowB + jj * 16) * 128 + ks * 32 + kbB));
                ldsm4(bh[jj], sbase + OFF_BH + off);
                ldsm4(bl[jj], sbase + OFF_BL + off);
            }
#pragma unroll
            for (int i = 0; i < 4; i++)
#pragma unroll
                for (int jj = 0; jj < 2; jj++)
#pragma unroll
                    for (int nb = 0; nb < 2; nb++) {
                        float* c = acc[i][jj * 2 + nb];
                        mma16816(c, ah[i], bh[jj][nb * 2], bh[jj][nb * 2 + 1]); // hi*hi
                        mma16816(c, ah[i], bl[jj][nb * 2], bl[jj][nb * 2 + 1]); // hi*lo
                        mma16816(c, al[i], bh[jj][nb * 2], bh[jj][nb * 2 + 1]); // lo*hi
                    }
        }

        if (kc + 1 < NKC) {
            CP_WAIT0();
            __syncthreads();                 // next-stage data landed; cur fully read
            convertA(smem + (size_t)(cur ^ 1) * STAGE_BYTES, tid);
            __syncthreads();                 // converted tiles visible
        }
    }

    // ---- epilogue ----
    const int qr = lane >> 2;          // row within m16
    const int qc = (lane & 3) * 2;     // col within n8
#pragma unroll
    for (int i = 0; i < 4; i++) {
        long long mr0 = m0 + wm * 64 + i * 16 + qr;
#pragma unroll
        for (int j = 0; j < 4; j++) {
            long long n = n0 + wn * 32 + j * 8 + qc;
            float* c = acc[i][j];
            if (EPI == 0) {
                float o0 = c[0], o1 = c[1], o2 = c[2], o3 = c[3];
                if (MASK) {
                    // mask[b][n(s1)][m(s2)], row stride S2V
                    if (mb[n * S2V + mr0])           o0 = NEG_INF;
                    if (mb[(n + 1) * S2V + mr0])     o1 = NEG_INF;
                    if (mb[n * S2V + mr0 + 8])       o2 = NEG_INF;
                    if (mb[(n + 1) * S2V + mr0 + 8]) o3 = NEG_INF;
                }
                *(float2*)(Cf + bz * sC + mr0 * (long long)N + n)       = make_float2(o0, o1);
                *(float2*)(Cf + bz * sC + (mr0 + 8) * (long long)N + n) = make_float2(o2, o3);
            } else {
                float b0 = bias[n], b1 = bias[n + 1];
#pragma unroll
                for (int h = 0; h < 2; h++) {
                    float x0 = c[2 * h]     + b0;
                    float x1 = c[2 * h + 1] + b1;
                    bf16 h0 = __float2bfloat16(x0);
                    bf16 h1 = __float2bfloat16(x1);
                    long long off = (mr0 + 8 * h) * (long long)N + n;
                    *(uint32_t*)(Ch + off) =
                        (uint32_t)__bfloat16_as_ushort(h0) | ((uint32_t)__bfloat16_as_ushort(h1) << 16);
                    *(uint32_t*)(Cl + off) = pack2(x0 - __bfloat162float(h0),
                                                   x1 - __bfloat162float(h1));
                }
            }
        }
    }
}

// ----------------------------------------------------------------------------
// fp32 -> hi/lo bf16 elementwise split (W only)
// ----------------------------------------------------------------------------
__global__ __launch_bounds__(256) void split_kernel(
    const float4* __restrict__ in, uint32_t* __restrict__ hi, uint32_t* __restrict__ lo)
{
    long long i = (long long)blockIdx.x * 256 + threadIdx.x;
    float4 v = in[i];
    bf16 h0 = __float2bfloat16(v.x), h1 = __float2bfloat16(v.y);
    bf16 h2 = __float2bfloat16(v.z), h3 = __float2bfloat16(v.w);
    hi[2 * i]     = (uint32_t)__bfloat16_as_ushort(h0) | ((uint32_t)__bfloat16_as_ushort(h1) << 16);
    hi[2 * i + 1] = (uint32_t)__bfloat16_as_ushort(h2) | ((uint32_t)__bfloat16_as_ushort(h3) << 16);
    lo[2 * i]     = pack2(v.x - __bfloat162float(h0), v.y - __bfloat162float(h1));
    lo[2 * i + 1] = pack2(v.z - __bfloat162float(h2), v.w - __bfloat162float(h3));
}

// ----------------------------------------------------------------------------
// value [B,S1,H] fp32 -> valueT hi/lo [B,H,S1] bf16
// ----------------------------------------------------------------------------
__global__ void transpose_split_value(const float* __restrict__ v,
                                      bf16* __restrict__ th, bf16* __restrict__ tl)
{
    __shared__ float tile[32][33];
    int b = blockIdx.z;
    int h0 = blockIdx.x * 32, s0 = blockIdx.y * 32;
    const float* vb = v + (size_t)b * S1V * HV;
    int tx = threadIdx.x, ty = threadIdx.y;
#pragma unroll
    for (int i = 0; i < 32; i += 8)
        tile[ty + i][tx] = vb[(size_t)(s0 + ty + i) * HV + h0 + tx];
    __syncthreads();
    size_t base = (size_t)b * HV * S1V;
#pragma unroll
    for (int i = 0; i < 32; i += 8) {
        float x = tile[tx][ty + i];
        bf16 h = __float2bfloat16(x);
        bf16 l = __float2bfloat16(x - __bfloat162float(h));
        size_t o = base + (size_t)(h0 + ty + i) * S1V + s0 + tx;
        th[o] = h;
        tl[o] = l;
    }
}

// ----------------------------------------------------------------------------
// softmax over S1 (scores already masked with -inf); writes fp32 weights only
// ----------------------------------------------------------------------------
__device__ __forceinline__ float warpMax(float v) {
#pragma unroll
    for (int o = 16; o > 0; o >>= 1) v = fmaxf(v, __shfl_xor_sync(0xffffffffu, v, o));
    return v;
}
__device__ __forceinline__ float warpSum(float v) {
#pragma unroll
    for (int o = 16; o > 0; o >>= 1) v += __shfl_xor_sync(0xffffffffu, v, o);
    return v;
}

__global__ __launch_bounds__(256) void softmax_kernel(
    const float* __restrict__ scores, float* __restrict__ weights)
{
    __shared__ float sred[8];
    __shared__ float sbc[2];

    const long long row = blockIdx.x;
    const float* s = scores + row * S1V;
    const int t = threadIdx.x, lane = t & 31, wid = t >> 5;

    float vals[8];
    float mx = -INFINITY;
#pragma unroll
    for (int i = 0; i < 8; i++) {
        float v = s[t + i * 256];
        vals[i] = v;
        mx = fmaxf(mx, v);
    }
    mx = warpMax(mx);
    if (lane == 0) sred[wid] = mx;
    __syncthreads();
    if (wid == 0) {
        float x = (lane < 8) ? sred[lane] : -INFINITY;
        x = warpMax(x);
        if (lane == 0) sbc[0] = x;
    }
    __syncthreads();
    mx = sbc[0];

    float sum = 0.f;
#pragma unroll
    for (int i = 0; i < 8; i++) { vals[i] = __expf(vals[i] - mx); sum += vals[i]; }
    sum = warpSum(sum);
    if (lane == 0) sred[wid] = sum;
    __syncthreads();
    if (wid == 0) {
        float x = (lane < 8) ? sred[lane] : 0.f;
        x = warpSum(x);
        if (lane == 0) sbc[1] = x;
    }
    __syncthreads();
    float inv = 1.f / sbc[1];
#pragma unroll
    for (int i = 0; i < 8; i++)
        weights[row * S1V + t + i * 256] = vals[i] * inv;
}

// ----------------------------------------------------------------------------
// kernel_launch
// Inputs: value, key, query, mask(int32), W, b.  Output: context | weights.
// ----------------------------------------------------------------------------
extern "C" void kernel_launch(void* const* d_in, const int* in_sizes, int n_in,
                              void* d_out, int out_size)
{
    const float* value = (const float*)d_in[0];
    const float* key   = (const float*)d_in[1];
    const float* query = (const float*)d_in[2];
    const int*   mask  = (const int*)d_in[3];
    const float* W     = (const float*)d_in[4];
    const float* bias  = (const float*)d_in[5];

    float* ctx     = (float*)d_out;                              // [B,S2,H]
    float* weights = (float*)d_out + (size_t)BATCH * S2V * HV;   // [B,S2,S1]

    bf16 *wh, *wl, *qph, *qpl, *vth, *vtl;
    float* scores;
    cudaGetSymbolAddress((void**)&wh,  g_wh);   cudaGetSymbolAddress((void**)&wl,  g_wl);
    cudaGetSymbolAddress((void**)&qph, g_qph);  cudaGetSymbolAddress((void**)&qpl, g_qpl);
    cudaGetSymbolAddress((void**)&vth, g_vth);  cudaGetSymbolAddress((void**)&vtl, g_vtl);
    cudaGetSymbolAddress((void**)&scores, g_scores);

    cudaFuncSetAttribute(mma_gemm<0,0>, cudaFuncAttributeMaxDynamicSharedMemorySize, SMEM_BYTES);
    cudaFuncSetAttribute(mma_gemm<0,1>, cudaFuncAttributeMaxDynamicSharedMemorySize, SMEM_BYTES);
    cudaFuncSetAttribute(mma_gemm<1,0>, cudaFuncAttributeMaxDynamicSharedMemorySize, SMEM_BYTES);

    // 1) prep: W split + value transpose/split
    split_kernel<<<(HV * HV) / 1024, 256>>>((const float4*)W, (uint32_t*)wh, (uint32_t*)wl);
    transpose_split_value<<<dim3(HV / 32, S1V / 32, BATCH), dim3(32, 8)>>>(value, vth, vtl);

    // 2) q_proj = query @ W^T + b -> qproj hi/lo  (M=16384, N=1024, K=1024)
    mma_gemm<1,0><<<dim3(HV / TILE_N, (BATCH * S1V) / TILE_M, 1), 256, SMEM_BYTES>>>(
        query, wh, wl, bias,
        nullptr, qph, qpl, nullptr,
        HV, HV, HV, HV, 0, 0, 0, 0);

    // 3) scoresT[b] = key[b] @ qproj[b]^T with fused mask  (M=S2, N=S1, K=H)
    mma_gemm<0,1><<<dim3(S1V / TILE_N, S2V / TILE_M, BATCH), 256, SMEM_BYTES>>>(
        key, qph, qpl, nullptr,
        scores, nullptr, nullptr, mask,
        HV, S1V, HV, HV,
        (long long)S2V * HV, (long long)S1V * HV, (long long)S2V * S1V,
        (long long)S1V * S2V);

    // 4) softmax over S1 -> weights (fp32, straight to output)
    softmax_kernel<<<BATCH * S2V, 256>>>(scores, weights);

    // 5) context[b] = weights[b] @ valueT[b]^T  (M=S2, N=H, K=S1; A=fp32 weights)
    mma_gemm<0,0><<<dim3(HV / TILE_N, S2V / TILE_M, BATCH), 256, SMEM_BYTES>>>(
        weights, vth, vtl, nullptr,
        ctx, nullptr, nullptr, nullptr,
        S1V, HV, S1V, S1V,
        (long long)S2V * S1V, (long long)HV * S1V, (long long)S2V * HV, 0);
}

// round 11
// speedup vs baseline: 1.0001x; 1.0001x over previous
#include <cuda_runtime.h>
#include <cuda_bf16.h>
#include <cstdint>
#include <math.h>

#define BATCH 8
#define S1V   2048
#define S2V   2048
#define HV    1024

typedef __nv_bfloat16 bf16;

// ----------------------------------------------------------------------------
// Scratch (device globals)
// ----------------------------------------------------------------------------
__device__ bf16 g_wh [(size_t)HV * HV];            // W hi/lo
__device__ bf16 g_wl [(size_t)HV * HV];
__device__ bf16 g_qph[(size_t)BATCH * S1V * HV];   // qproj hi/lo
__device__ bf16 g_qpl[(size_t)BATCH * S1V * HV];
__device__ bf16 g_vth[(size_t)BATCH * HV * S1V];   // valueT hi/lo [B,H,S1]
__device__ bf16 g_vtl[(size_t)BATCH * HV * S1V];
__device__ float g_scores[(size_t)BATCH * S2V * S1V];  // masked logits [B,S2,S1]

#define NEG_INF __int_as_float(0xff800000)

// ----------------------------------------------------------------------------
// PTX helpers (plain sm_80+ features only)
// ----------------------------------------------------------------------------
__device__ __forceinline__ uint32_t smem_u32(const void* p) {
    uint32_t a;
    asm("{ .reg .u64 t; cvta.to.shared.u64 t, %1; cvt.u32.u64 %0, t; }" : "=r"(a) : "l"(p));
    return a;
}
__device__ __forceinline__ void cp_async16(uint32_t dst, const void* src) {
    asm volatile("cp.async.cg.shared.global [%0], [%1], 16;" :: "r"(dst), "l"(src));
}
#define CP_COMMIT() asm volatile("cp.async.commit_group;" ::: "memory")
#define CP_WAIT0()  asm volatile("cp.async.wait_group 0;" ::: "memory")

__device__ __forceinline__ void ldsm4(uint32_t r[4], uint32_t addr) {
    asm volatile("ldmatrix.sync.aligned.m8n8.x4.shared.b16 {%0,%1,%2,%3}, [%4];"
                 : "=r"(r[0]), "=r"(r[1]), "=r"(r[2]), "=r"(r[3]) : "r"(addr));
}
__device__ __forceinline__ void mma16816(float c[4], const uint32_t a[4],
                                         const uint32_t b0, const uint32_t b1) {
    asm volatile("mma.sync.aligned.m16n8k16.row.col.f32.bf16.bf16.f32 "
                 "{%0,%1,%2,%3}, {%4,%5,%6,%7}, {%8,%9}, {%0,%1,%2,%3};"
                 : "+f"(c[0]), "+f"(c[1]), "+f"(c[2]), "+f"(c[3])
                 : "r"(a[0]), "r"(a[1]), "r"(a[2]), "r"(a[3]), "r"(b0), "r"(b1));
}

#define SWZ(o) ((o) ^ (((o) >> 3) & 0x70))

__device__ __forceinline__ uint32_t pack2(float x0, float x1) {
    bf16 h0 = __float2bfloat16(x0), h1 = __float2bfloat16(x1);
    return (uint32_t)__bfloat16_as_ushort(h0) | ((uint32_t)__bfloat16_as_ushort(h1) << 16);
}

// ----------------------------------------------------------------------------
// Split-bf16 NT GEMM on mma.sync:  C[M,N] = A_fp32[M,K] @ (Bh+Bl)[N,K]^T
// A is fp32 in GMEM; each chunk is cp.async'd raw, then split into hi/lo bf16
// swizzled tiles in smem (same byte traffic as pre-split hi+lo).
// Block tile 128x128, K-chunk 64, 2-stage pipeline, 8 warps (2M x 4N),
// warp tile 64x32, 3 split passes (hi*hi + hi*lo + lo*hi) in fp32 accum.
// EPI: 0 = fp32 store (optional mask -> -inf); 1 = +bias, hi/lo split store.
// ----------------------------------------------------------------------------
#define TILE_M 128
#define TILE_N 128
#define TILE_K 64
#define OFF_AF 0          // 32KB fp32 A staging
#define OFF_AH 32768      // 16KB A hi tile (SW128)
#define OFF_AL 49152      // 16KB A lo tile
#define OFF_BH 65536      // 16KB B hi tile
#define OFF_BL 81920      // 16KB B lo tile
#define STAGE_BYTES 98304
#define SMEM_BYTES  (2 * STAGE_BYTES)

__device__ __forceinline__ void load_stage(
    uint32_t sbase,
    const float* A, const bf16* Bh, const bf16* Bl,
    long long m0, long long n0, long long ldA, long long ldB, int k0, int tid)
{
    // A fp32: 128 rows x 256B, plain row-major staging
#pragma unroll
    for (int i = tid; i < 2048; i += 256) {
        int r = i >> 4, c = i & 15;
        cp_async16(sbase + OFF_AF + r * 256 + c * 16, A + (m0 + r) * ldA + k0 + c * 4);
    }
    // B bf16 hi/lo: 128 rows x 128B each, SW128 swizzled
#pragma unroll
    for (int i = tid; i < 1024; i += 256) {
        int r = i >> 3, c = i & 7;
        uint32_t sw = SWZ(r * 128 + c * 16);
        long long goff = (n0 + r) * ldB + k0 + c * 8;
        cp_async16(sbase + OFF_BH + sw, Bh + goff);
        cp_async16(sbase + OFF_BL + sw, Bl + goff);
    }
}

__device__ __forceinline__ void convertA(char* stage, int tid)
{
    // 8192 fp32 -> hi/lo bf16 swizzled tiles; 8 float4 per thread
#pragma unroll
    for (int i = 0; i < 8; i++) {
        int j = tid + i * 256;
        int row = j >> 4;
        int c4  = (j & 15) * 4;            // first float col of this quad
        float4 v = *(const float4*)(stage + OFF_AF + (size_t)j * 16);
        bf16 h0 = __float2bfloat16(v.x), h1 = __float2bfloat16(v.y);
        bf16 h2 = __float2bfloat16(v.z), h3 = __float2bfloat16(v.w);
        float r0 = v.x - __bfloat162float(h0), r1 = v.y - __bfloat162float(h1);
        float r2 = v.z - __bfloat162float(h2), r3 = v.w - __bfloat162float(h3);
        uint2 hp, lp;
        hp.x = (uint32_t)__bfloat16_as_ushort(h0) | ((uint32_t)__bfloat16_as_ushort(h1) << 16);
        hp.y = (uint32_t)__bfloat16_as_ushort(h2) | ((uint32_t)__bfloat16_as_ushort(h3) << 16);
        lp.x = pack2(r0, r1);
        lp.y = pack2(r2, r3);
        uint32_t sw = SWZ((uint32_t)(row * 128 + c4 * 2));
        *(uint2*)(stage + OFF_AH + sw) = hp;
        *(uint2*)(stage + OFF_AL + sw) = lp;
    }
}

template <int EPI, int MASK>
__global__ __launch_bounds__(256) void mma_gemm(
    const float* __restrict__ A,
    const bf16* __restrict__ Bh, const bf16* __restrict__ Bl,
    const float* __restrict__ bias,
    float* __restrict__ Cf, bf16* __restrict__ Ch, bf16* __restrict__ Cl,
    const int* __restrict__ maskp,
    int K, int N,
    long long ldA, long long ldB,
    long long sA, long long sB, long long sC, long long sMask)
{
    extern __shared__ char smem[];
    const uint32_t sb = smem_u32(smem);

    const int tid  = threadIdx.x;
    const int wid  = tid >> 5;
    const int lane = tid & 31;
    const int wm = wid & 1;      // 2 M-groups of 64
    const int wn = wid >> 1;     // 4 N-groups of 32

    const long long bz = blockIdx.z;
    A  += bz * sA;
    Bh += bz * sB;  Bl += bz * sB;
    const int* mb = MASK ? (maskp + bz * sMask) : nullptr;
    const long long m0 = (long long)blockIdx.y * TILE_M;
    const long long n0 = (long long)blockIdx.x * TILE_N;

    // ldmatrix lane addressing
    const int g  = lane >> 3;
    const int lr = lane & 7;
    const int rowA = wm * 64 + (g & 1) * 8 + lr;
    const int kbA  = (g >> 1) * 16;
    const int rowB = wn * 32 + (g >> 1) * 8 + lr;
    const int kbB  = (g & 1) * 16;

    float acc[4][4][4];
#pragma unroll
    for (int i = 0; i < 4; i++)
#pragma unroll
        for (int j = 0; j < 4; j++)
#pragma unroll
            for (int r = 0; r < 4; r++) acc[i][j][r] = 0.f;

    const int NKC = K / TILE_K;

    // prologue: stage 0 load + convert
    load_stage(sb, A, Bh, Bl, m0, n0, ldA, ldB, 0, tid);
    CP_COMMIT();
    CP_WAIT0();
    __syncthreads();
    convertA(smem, tid);
    __syncthreads();

    for (int kc = 0; kc < NKC; ++kc) {
        const int cur = kc & 1;
        const uint32_t sbase = sb + cur * STAGE_BYTES;
        char* curp = smem + (size_t)cur * STAGE_BYTES;
        (void)curp;

        if (kc + 1 < NKC) {
            load_stage(sb + (cur ^ 1) * STAGE_BYTES, A, Bh, Bl,
                       m0, n0, ldA, ldB, (kc + 1) * TILE_K, tid);
            CP_COMMIT();
        }

        // ---- MMAs on current stage ----
#pragma unroll
        for (int ks = 0; ks < 4; ++ks) {
            uint32_t ah[4][4], al[4][4];
#pragma unroll
            for (int i = 0; i < 4; i++) {
                uint32_t off = SWZ((uint32_t)((rowA + i * 16) * 128 + ks * 32 + kbA));
                ldsm4(ah[i], sbase + OFF_AH + off);
                ldsm4(al[i], sbase + OFF_AL + off);
            }
            uint32_t bh[2][4], bl[2][4];
#pragma unroll
            for (int jj = 0; jj < 2; jj++) {
                uint32_t off = SWZ((uint32_t)((rowB + jj * 16) * 128 + ks * 32 + kbB));
                ldsm4(bh[jj], sbase + OFF_BH + off);
                ldsm4(bl[jj], sbase + OFF_BL + off);
            }
#pragma unroll
            for (int i = 0; i < 4; i++)
#pragma unroll
                for (int jj = 0; jj < 2; jj++)
#pragma unroll
                    for (int nb = 0; nb < 2; nb++) {
                        float* c = acc[i][jj * 2 + nb];
                        mma16816(c, ah[i], bh[jj][nb * 2], bh[jj][nb * 2 + 1]); // hi*hi
                        mma16816(c, ah[i], bl[jj][nb * 2], bl[jj][nb * 2 + 1]); // hi*lo
                        mma16816(c, al[i], bh[jj][nb * 2], bh[jj][nb * 2 + 1]); // lo*hi
                    }
        }

        if (kc + 1 < NKC) {
            CP_WAIT0();
            __syncthreads();                 // next-stage data landed; cur fully read
            convertA(smem + (size_t)(cur ^ 1) * STAGE_BYTES, tid);
            __syncthreads();                 // converted tiles visible
        }
    }

    // ---- epilogue ----
    const int qr = lane >> 2;          // row within m16
    const int qc = (lane & 3) * 2;     // col within n8
#pragma unroll
    for (int i = 0; i < 4; i++) {
        long long mr0 = m0 + wm * 64 + i * 16 + qr;
#pragma unroll
        for (int j = 0; j < 4; j++) {
            long long n = n0 + wn * 32 + j * 8 + qc;
            float* c = acc[i][j];
            if (EPI == 0) {
                float o0 = c[0], o1 = c[1], o2 = c[2], o3 = c[3];
                if (MASK) {
                    // mask[b][n(s1)][m(s2)], row stride S2V
                    if (mb[n * S2V + mr0])           o0 = NEG_INF;
                    if (mb[(n + 1) * S2V + mr0])     o1 = NEG_INF;
                    if (mb[n * S2V + mr0 + 8])       o2 = NEG_INF;
                    if (mb[(n + 1) * S2V + mr0 + 8]) o3 = NEG_INF;
                }
                *(float2*)(Cf + bz * sC + mr0 * (long long)N + n)       = make_float2(o0, o1);
                *(float2*)(Cf + bz * sC + (mr0 + 8) * (long long)N + n) = make_float2(o2, o3);
            } else {
                float b0 = bias[n], b1 = bias[n + 1];
#pragma unroll
                for (int h = 0; h < 2; h++) {
                    float x0 = c[2 * h]     + b0;
                    float x1 = c[2 * h + 1] + b1;
                    bf16 h0 = __float2bfloat16(x0);
                    bf16 h1 = __float2bfloat16(x1);
                    long long off = (mr0 + 8 * h) * (long long)N + n;
                    *(uint32_t*)(Ch + off) =
                        (uint32_t)__bfloat16_as_ushort(h0) | ((uint32_t)__bfloat16_as_ushort(h1) << 16);
                    *(uint32_t*)(Cl + off) = pack2(x0 - __bfloat162float(h0),
                                                   x1 - __bfloat162float(h1));
                }
            }
        }
    }
}

// ----------------------------------------------------------------------------
// fp32 -> hi/lo bf16 elementwise split (W only)
// ----------------------------------------------------------------------------
__global__ __launch_bounds__(256) void split_kernel(
    const float4* __restrict__ in, uint32_t* __restrict__ hi, uint32_t* __restrict__ lo)
{
    long long i = (long long)blockIdx.x * 256 + threadIdx.x;
    float4 v = in[i];
    bf16 h0 = __float2bfloat16(v.x), h1 = __float2bfloat16(v.y);
    bf16 h2 = __float2bfloat16(v.z), h3 = __float2bfloat16(v.w);
    hi[2 * i]     = (uint32_t)__bfloat16_as_ushort(h0) | ((uint32_t)__bfloat16_as_ushort(h1) << 16);
    hi[2 * i + 1] = (uint32_t)__bfloat16_as_ushort(h2) | ((uint32_t)__bfloat16_as_ushort(h3) << 16);
    lo[2 * i]     = pack2(v.x - __bfloat162float(h0), v.y - __bfloat162float(h1));
    lo[2 * i + 1] = pack2(v.z - __bfloat162float(h2), v.w - __bfloat162float(h3));
}

// ----------------------------------------------------------------------------
// value [B,S1,H] fp32 -> valueT hi/lo [B,H,S1] bf16
// ----------------------------------------------------------------------------
__global__ void transpose_split_value(const float* __restrict__ v,
                                      bf16* __restrict__ th, bf16* __restrict__ tl)
{
    __shared__ float tile[32][33];
    int b = blockIdx.z;
    int h0 = blockIdx.x * 32, s0 = blockIdx.y * 32;
    const float* vb = v + (size_t)b * S1V * HV;
    int tx = threadIdx.x, ty = threadIdx.y;
#pragma unroll
    for (int i = 0; i < 32; i += 8)
        tile[ty + i][tx] = vb[(size_t)(s0 + ty + i) * HV + h0 + tx];
    __syncthreads();
    size_t base = (size_t)b * HV * S1V;
#pragma unroll
    for (int i = 0; i < 32; i += 8) {
        float x = tile[tx][ty + i];
        bf16 h = __float2bfloat16(x);
        bf16 l = __float2bfloat16(x - __bfloat162float(h));
        size_t o = base + (size_t)(h0 + ty + i) * S1V + s0 + tx;
        th[o] = h;
        tl[o] = l;
    }
}

// ----------------------------------------------------------------------------
// softmax over S1 (scores already masked with -inf); writes fp32 weights only
// ----------------------------------------------------------------------------
__device__ __forceinline__ float warpMax(float v) {
#pragma unroll
    for (int o = 16; o > 0; o >>= 1) v = fmaxf(v, __shfl_xor_sync(0xffffffffu, v, o));
    return v;
}
__device__ __forceinline__ float warpSum(float v) {
#pragma unroll
    for (int o = 16; o > 0; o >>= 1) v += __shfl_xor_sync(0xffffffffu, v, o);
    return v;
}

__global__ __launch_bounds__(256) void softmax_kernel(
    const float* __restrict__ scores, float* __restrict__ weights)
{
    __shared__ float sred[8];
    __shared__ float sbc[2];

    const long long row = blockIdx.x;
    const float* s = scores + row * S1V;
    const int t = threadIdx.x, lane = t & 31, wid = t >> 5;

    float vals[8];
    float mx = -INFINITY;
#pragma unroll
    for (int i = 0; i < 8; i++) {
        float v = s[t + i * 256];
        vals[i] = v;
        mx = fmaxf(mx, v);
    }
    mx = warpMax(mx);
    if (lane == 0) sred[wid] = mx;
    __syncthreads();
    if (wid == 0) {
        float x = (lane < 8) ? sred[lane] : -INFINITY;
        x = warpMax(x);
        if (lane == 0) sbc[0] = x;
    }
    __syncthreads();
    mx = sbc[0];

    float sum = 0.f;
#pragma unroll
    for (int i = 0; i < 8; i++) { vals[i] = __expf(vals[i] - mx); sum += vals[i]; }
    sum = warpSum(sum);
    if (lane == 0) sred[wid] = sum;
    __syncthreads();
    if (wid == 0) {
        float x = (lane < 8) ? sred[lane] : 0.f;
        x = warpSum(x);
        if (lane == 0) sbc[1] = x;
    }
    __syncthreads();
    float inv = 1.f / sbc[1];
#pragma unroll
    for (int i = 0; i < 8; i++)
        weights[row * S1V + t + i * 256] = vals[i] * inv;
}

// ----------------------------------------------------------------------------
// kernel_launch
// Inputs: value, key, query, mask(int32), W, b.  Output: context | weights.
// ----------------------------------------------------------------------------
extern "C" void kernel_launch(void* const* d_in, const int* in_sizes, int n_in,
                              void* d_out, int out_size)
{
    const float* value = (const float*)d_in[0];
    const float* key   = (const float*)d_in[1];
    const float* query = (const float*)d_in[2];
    const int*   mask  = (const int*)d_in[3];
    const float* W     = (const float*)d_in[4];
    const float* bias  = (const float*)d_in[5];

    float* ctx     = (float*)d_out;                              // [B,S2,H]
    float* weights = (float*)d_out + (size_t)BATCH * S2V * HV;   // [B,S2,S1]

    bf16 *wh, *wl, *qph, *qpl, *vth, *vtl;
    float* scores;
    cudaGetSymbolAddress((void**)&wh,  g_wh);   cudaGetSymbolAddress((void**)&wl,  g_wl);
    cudaGetSymbolAddress((void**)&qph, g_qph);  cudaGetSymbolAddress((void**)&qpl, g_qpl);
    cudaGetSymbolAddress((void**)&vth, g_vth);  cudaGetSymbolAddress((void**)&vtl, g_vtl);
    cudaGetSymbolAddress((void**)&scores, g_scores);

    cudaFuncSetAttribute(mma_gemm<0,0>, cudaFuncAttributeMaxDynamicSharedMemorySize, SMEM_BYTES);
    cudaFuncSetAttribute(mma_gemm<0,1>, cudaFuncAttributeMaxDynamicSharedMemorySize, SMEM_BYTES);
    cudaFuncSetAttribute(mma_gemm<1,0>, cudaFuncAttributeMaxDynamicSharedMemorySize, SMEM_BYTES);

    // 1) prep: W split + value transpose/split
    split_kernel<<<(HV * HV) / 1024, 256>>>((const float4*)W, (uint32_t*)wh, (uint32_t*)wl);
    transpose_split_value<<<dim3(HV / 32, S1V / 32, BATCH), dim3(32, 8)>>>(value, vth, vtl);

    // 2) q_proj = query @ W^T + b -> qproj hi/lo  (M=16384, N=1024, K=1024)
    mma_gemm<1,0><<<dim3(HV / TILE_N, (BATCH * S1V) / TILE_M, 1), 256, SMEM_BYTES>>>(
        query, wh, wl, bias,
        nullptr, qph, qpl, nullptr,
        HV, HV, HV, HV, 0, 0, 0, 0);

    // 3) scoresT[b] = key[b] @ qproj[b]^T with fused mask  (M=S2, N=S1, K=H)
    mma_gemm<0,1><<<dim3(S1V / TILE_N, S2V / TILE_M, BATCH), 256, SMEM_BYTES>>>(
        key, qph, qpl, nullptr,
        scores, nullptr, nullptr, mask,
        HV, S1V, HV, HV,
        (long long)S2V * HV, (long long)S1V * HV, (long long)S2V * S1V,
        (long long)S1V * S2V);

    // 4) softmax over S1 -> weights (fp32, straight to output)
    softmax_kernel<<<BATCH * S2V, 256>>>(scores, weights);

    // 5) context[b] = weights[b] @ valueT[b]^T  (M=S2, N=H, K=S1; A=fp32 weights)
    mma_gemm<0,0><<<dim3(HV / TILE_N, S2V / TILE_M, BATCH), 256, SMEM_BYTES>>>(
        weights, vth, vtl, nullptr,
        ctx, nullptr, nullptr, nullptr,
        S1V, HV, S1V, S1V,
        (long long)S2V * S1V, (long long)HV * S1V, (long long)S2V * HV, 0);
}

// round 12
// speedup vs baseline: 1.3087x; 1.3085x over previous
#include <cuda_runtime.h>
#include <cuda_bf16.h>
#include <cstdint>
#include <math.h>

#define BATCH 8
#define S1V   2048
#define S2V   2048
#define HV    1024

typedef __nv_bfloat16 bf16;

// ----------------------------------------------------------------------------
// Scratch (device globals)
// ----------------------------------------------------------------------------
__device__ bf16 g_qh [(size_t)BATCH * S1V * HV];
__device__ bf16 g_ql [(size_t)BATCH * S1V * HV];
__device__ bf16 g_kh [(size_t)BATCH * S2V * HV];
__device__ bf16 g_kl [(size_t)BATCH * S2V * HV];
__device__ bf16 g_wh [(size_t)HV * HV];
__device__ bf16 g_wl [(size_t)HV * HV];
__device__ bf16 g_qph[(size_t)BATCH * S1V * HV];
__device__ bf16 g_qpl[(size_t)BATCH * S1V * HV];
__device__ bf16 g_vth[(size_t)BATCH * HV * S1V];   // valueT [B,H,S1]
__device__ bf16 g_vtl[(size_t)BATCH * HV * S1V];
__device__ bf16 g_wgh[(size_t)BATCH * S2V * S1V];
__device__ bf16 g_wgl[(size_t)BATCH * S2V * S1V];
__device__ float g_scores[(size_t)BATCH * S2V * S1V];  // masked logits [B,S2,S1]

#define NEG_INF __int_as_float(0xff800000)

// ----------------------------------------------------------------------------
// PTX helpers (plain sm_80+ features only)
// ----------------------------------------------------------------------------
__device__ __forceinline__ void cp_async16(uint32_t dst, const void* src) {
    asm volatile("cp.async.cg.shared.global [%0], [%1], 16;" :: "r"(dst), "l"(src));
}
__device__ __forceinline__ uint32_t smem_u32(const void* p) {
    uint32_t a;
    asm("{ .reg .u64 t; cvta.to.shared.u64 t, %1; cvt.u32.u64 %0, t; }" : "=r"(a) : "l"(p));
    return a;
}
#define CP_COMMIT() asm volatile("cp.async.commit_group;" ::: "memory")
#define CP_WAIT0()  asm volatile("cp.async.wait_group 0;" ::: "memory")
#define CP_WAIT1()  asm volatile("cp.async.wait_group 1;" ::: "memory")

__device__ __forceinline__ void ldsm4(uint32_t r[4], uint32_t addr) {
    asm volatile("ldmatrix.sync.aligned.m8n8.x4.shared.b16 {%0,%1,%2,%3}, [%4];"
                 : "=r"(r[0]), "=r"(r[1]), "=r"(r[2]), "=r"(r[3]) : "r"(addr));
}
__device__ __forceinline__ void mma16816(float c[4], const uint32_t a[4],
                                         const uint32_t b0, const uint32_t b1) {
    asm volatile("mma.sync.aligned.m16n8k16.row.col.f32.bf16.bf16.f32 "
                 "{%0,%1,%2,%3}, {%4,%5,%6,%7}, {%8,%9}, {%0,%1,%2,%3};"
                 : "+f"(c[0]), "+f"(c[1]), "+f"(c[2]), "+f"(c[3])
                 : "r"(a[0]), "r"(a[1]), "r"(a[2]), "r"(a[3]), "r"(b0), "r"(b1));
}

#define SWZ(o) ((o) ^ (((o) >> 3) & 0x70))

__device__ __forceinline__ uint32_t pack2(float x0, float x1) {
    bf16 h0 = __float2bfloat16(x0), h1 = __float2bfloat16(x1);
    return (uint32_t)__bfloat16_as_ushort(h0) | ((uint32_t)__bfloat16_as_ushort(h1) << 16);
}

// ----------------------------------------------------------------------------
// Split-bf16 NT GEMM on mma.sync:  C[M,N] = (Ah+Al)[M,K] @ (Bh+Bl)[N,K]^T
// Block tile 128x128, K-chunk 64, SW128 smem, 2-stage cp.async pipeline.
// 8 warps 2(M) x 4(N); warp tile 64x32.  3 split passes, PASS-MAJOR ordering
// (16 independent accumulators per pass -> no MMA RAW chains).
// EPI: 0 = fp32 store (+ optional fused mask -> -inf); 1 = +bias, hi/lo split.
// ----------------------------------------------------------------------------
#define TILE_M 128
#define TILE_N 128
#define TILE_K 64
#define STAGE_BYTES 65536   // Ah 16K | Al 16K | Bh 16K | Bl 16K
#define SMEM_BYTES  (2 * STAGE_BYTES)

__device__ __forceinline__ void load_stage(
    uint32_t sbase,
    const bf16* Ah, const bf16* Al, const bf16* Bh, const bf16* Bl,
    long long m0, long long n0, long long ldA, long long ldB, int k0, int tid)
{
#pragma unroll
    for (int i = tid; i < 1024; i += 256) {            // A: 128 rows x 128B
        int r = i >> 3, c = i & 7;
        uint32_t sw = SWZ(r * 128 + c * 16);
        long long goff = (m0 + r) * ldA + k0 + c * 8;
        cp_async16(sbase + sw,         Ah + goff);
        cp_async16(sbase + 16384 + sw, Al + goff);
    }
#pragma unroll
    for (int i = tid; i < 1024; i += 256) {            // B: 128 rows x 128B
        int r = i >> 3, c = i & 7;
        uint32_t sw = SWZ(r * 128 + c * 16);
        long long goff = (n0 + r) * ldB + k0 + c * 8;
        cp_async16(sbase + 32768 + sw, Bh + goff);
        cp_async16(sbase + 49152 + sw, Bl + goff);
    }
}

template <int EPI, int MASK>
__global__ __launch_bounds__(256) void mma_gemm(
    const bf16* __restrict__ Ah, const bf16* __restrict__ Al,
    const bf16* __restrict__ Bh, const bf16* __restrict__ Bl,
    const float* __restrict__ bias,
    float* __restrict__ Cf, bf16* __restrict__ Ch, bf16* __restrict__ Cl,
    const int* __restrict__ maskp,
    int K, int N,
    long long ldA, long long ldB,
    long long sA, long long sB, long long sC, long long sMask)
{
    extern __shared__ char smem[];
    const uint32_t sb = smem_u32(smem);

    const int tid  = threadIdx.x;
    const int wid  = tid >> 5;
    const int lane = tid & 31;
    const int wm = wid & 1;      // 2 M-groups of 64
    const int wn = wid >> 1;     // 4 N-groups of 32

    const long long bz = blockIdx.z;
    Ah += bz * sA;  Al += bz * sA;
    Bh += bz * sB;  Bl += bz * sB;
    const int* mb = MASK ? (maskp + bz * sMask) : nullptr;
    const long long m0 = (long long)blockIdx.y * TILE_M;
    const long long n0 = (long long)blockIdx.x * TILE_N;

    // ldmatrix lane addressing (tile index g = lane>>3):
    const int g  = lane >> 3;
    const int lr = lane & 7;
    const int rowA = wm * 64 + (g & 1) * 8 + lr;
    const int kbA  = (g >> 1) * 16;
    const int rowB = wn * 32 + (g >> 1) * 8 + lr;
    const int kbB  = (g & 1) * 16;

    float acc[4][4][4];
#pragma unroll
    for (int i = 0; i < 4; i++)
#pragma unroll
        for (int j = 0; j < 4; j++)
#pragma unroll
            for (int r = 0; r < 4; r++) acc[i][j][r] = 0.f;

    const int NKC = K / TILE_K;

    load_stage(sb, Ah, Al, Bh, Bl, m0, n0, ldA, ldB, 0, tid);
    CP_COMMIT();

    for (int kc = 0; kc < NKC; ++kc) {
        const uint32_t sbase = sb + (kc & 1) * STAGE_BYTES;
        if (kc + 1 < NKC) {
            load_stage(sb + ((kc + 1) & 1) * STAGE_BYTES,
                       Ah, Al, Bh, Bl, m0, n0, ldA, ldB, (kc + 1) * TILE_K, tid);
            CP_COMMIT();
            CP_WAIT1();
        } else {
            CP_WAIT0();
        }
        __syncthreads();

#pragma unroll
        for (int ks = 0; ks < 4; ++ks) {
            uint32_t ah[4][4], al[4][4];
#pragma unroll
            for (int i = 0; i < 4; i++) {
                uint32_t off = SWZ((uint32_t)((rowA + i * 16) * 128 + ks * 32 + kbA));
                ldsm4(ah[i], sbase + off);
                ldsm4(al[i], sbase + 16384 + off);
            }
            uint32_t bh[2][4], bl[2][4];
#pragma unroll
            for (int jj = 0; jj < 2; jj++) {
                uint32_t off = SWZ((uint32_t)((rowB + jj * 16) * 128 + ks * 32 + kbB));
                ldsm4(bh[jj], sbase + 32768 + off);
                ldsm4(bl[jj], sbase + 49152 + off);
            }
            // Pass-major: 16 independent accumulators per pass -> no RAW chain
#pragma unroll
            for (int i = 0; i < 4; i++)                       // hi * hi
#pragma unroll
                for (int jj = 0; jj < 2; jj++)
#pragma unroll
                    for (int nb = 0; nb < 2; nb++)
                        mma16816(acc[i][jj * 2 + nb], ah[i], bh[jj][nb * 2], bh[jj][nb * 2 + 1]);
#pragma unroll
            for (int i = 0; i < 4; i++)                       // hi * lo
#pragma unroll
                for (int jj = 0; jj < 2; jj++)
#pragma unroll
                    for (int nb = 0; nb < 2; nb++)
                        mma16816(acc[i][jj * 2 + nb], ah[i], bl[jj][nb * 2], bl[jj][nb * 2 + 1]);
#pragma unroll
            for (int i = 0; i < 4; i++)                       // lo * hi
#pragma unroll
                for (int jj = 0; jj < 2; jj++)
#pragma unroll
                    for (int nb = 0; nb < 2; nb++)
                        mma16816(acc[i][jj * 2 + nb], al[i], bh[jj][nb * 2], bh[jj][nb * 2 + 1]);
        }
        __syncthreads();
    }

    // ---- epilogue ----
    const int qr = lane >> 2;          // row within m16
    const int qc = (lane & 3) * 2;     // col within n8
#pragma unroll
    for (int i = 0; i < 4; i++) {
        long long mr0 = m0 + wm * 64 + i * 16 + qr;
#pragma unroll
        for (int j = 0; j < 4; j++) {
            long long n = n0 + wn * 32 + j * 8 + qc;
            float* c = acc[i][j];
            if (EPI == 0) {
                float o0 = c[0], o1 = c[1], o2 = c[2], o3 = c[3];
                if (MASK) {
                    // mask[b][n(s1)][m(s2)], row stride S2V
                    if (mb[n * S2V + mr0])           o0 = NEG_INF;
                    if (mb[(n + 1) * S2V + mr0])     o1 = NEG_INF;
                    if (mb[n * S2V + mr0 + 8])       o2 = NEG_INF;
                    if (mb[(n + 1) * S2V + mr0 + 8]) o3 = NEG_INF;
                }
                *(float2*)(Cf + bz * sC + mr0 * (long long)N + n)       = make_float2(o0, o1);
                *(float2*)(Cf + bz * sC + (mr0 + 8) * (long long)N + n) = make_float2(o2, o3);
            } else {
                float b0 = bias[n], b1 = bias[n + 1];
#pragma unroll
                for (int h = 0; h < 2; h++) {
                    float x0 = c[2 * h]     + b0;
                    float x1 = c[2 * h + 1] + b1;
                    bf16 h0 = __float2bfloat16(x0);
                    bf16 h1 = __float2bfloat16(x1);
                    long long off = (mr0 + 8 * h) * (long long)N + n;
                    *(uint32_t*)(Ch + off) =
                        (uint32_t)__bfloat16_as_ushort(h0) | ((uint32_t)__bfloat16_as_ushort(h1) << 16);
                    *(uint32_t*)(Cl + off) = pack2(x0 - __bfloat162float(h0),
                                                   x1 - __bfloat162float(h1));
                }
            }
        }
    }
}

// ----------------------------------------------------------------------------
// fp32 -> hi/lo bf16 elementwise split
// ----------------------------------------------------------------------------
__global__ __launch_bounds__(256) void split_kernel(
    const float4* __restrict__ in, uint32_t* __restrict__ hi, uint32_t* __restrict__ lo)
{
    long long i = (long long)blockIdx.x * 256 + threadIdx.x;
    float4 v = in[i];
    bf16 h0 = __float2bfloat16(v.x), h1 = __float2bfloat16(v.y);
    bf16 h2 = __float2bfloat16(v.z), h3 = __float2bfloat16(v.w);
    hi[2 * i]     = (uint32_t)__bfloat16_as_ushort(h0) | ((uint32_t)__bfloat16_as_ushort(h1) << 16);
    hi[2 * i + 1] = (uint32_t)__bfloat16_as_ushort(h2) | ((uint32_t)__bfloat16_as_ushort(h3) << 16);
    lo[2 * i]     = pack2(v.x - __bfloat162float(h0), v.y - __bfloat162float(h1));
    lo[2 * i + 1] = pack2(v.z - __bfloat162float(h2), v.w - __bfloat162float(h3));
}

// ----------------------------------------------------------------------------
// value [B,S1,H] fp32 -> valueT hi/lo [B,H,S1] bf16
// ----------------------------------------------------------------------------
__global__ void transpose_split_value(const float* __restrict__ v,
                                      bf16* __restrict__ th, bf16* __restrict__ tl)
{
    __shared__ float tile[32][33];
    int b = blockIdx.z;
    int h0 = blockIdx.x * 32, s0 = blockIdx.y * 32;
    const float* vb = v + (size_t)b * S1V * HV;
    int tx = threadIdx.x, ty = threadIdx.y;
#pragma unroll
    for (int i = 0; i < 32; i += 8)
        tile[ty + i][tx] = vb[(size_t)(s0 + ty + i) * HV + h0 + tx];
    __syncthreads();
    size_t base = (size_t)b * HV * S1V;
#pragma unroll
    for (int i = 0; i < 32; i += 8) {
        float x = tile[tx][ty + i];
        bf16 h = __float2bfloat16(x);
        bf16 l = __float2bfloat16(x - __bfloat162float(h));
        size_t o = base + (size_t)(h0 + ty + i) * S1V + s0 + tx;
        th[o] = h;
        tl[o] = l;
    }
}

// ----------------------------------------------------------------------------
// softmax over S1 (scores pre-masked with -inf in GEMM2 epilogue);
// writes fp32 weights (output) + hi/lo bf16 (for GEMM3)
// ----------------------------------------------------------------------------
__device__ __forceinline__ float warpMax(float v) {
#pragma unroll
    for (int o = 16; o > 0; o >>= 1) v = fmaxf(v, __shfl_xor_sync(0xffffffffu, v, o));
    return v;
}
__device__ __forceinline__ float warpSum(float v) {
#pragma unroll
    for (int o = 16; o > 0; o >>= 1) v += __shfl_xor_sync(0xffffffffu, v, o);
    return v;
}

__global__ __launch_bounds__(256) void softmax_kernel(
    const float* __restrict__ scores,
    float* __restrict__ weights, bf16* __restrict__ wh, bf16* __restrict__ wl)
{
    __shared__ float sred[8];
    __shared__ float sbc[2];

    const long long row = blockIdx.x;
    const float* s = scores + row * S1V;
    const int t = threadIdx.x, lane = t & 31, wid = t >> 5;

    float vals[8];
    float mx = -INFINITY;
#pragma unroll
    for (int i = 0; i < 8; i++) {
        float v = s[t + i * 256];
        vals[i] = v;
        mx = fmaxf(mx, v);
    }
    mx = warpMax(mx);
    if (lane == 0) sred[wid] = mx;
    __syncthreads();
    if (wid == 0) {
        float x = (lane < 8) ? sred[lane] : -INFINITY;
        x = warpMax(x);
        if (lane == 0) sbc[0] = x;
    }
    __syncthreads();
    mx = sbc[0];

    float sum = 0.f;
#pragma unroll
    for (int i = 0; i < 8; i++) { vals[i] = __expf(vals[i] - mx); sum += vals[i]; }
    sum = warpSum(sum);
    if (lane == 0) sred[wid] = sum;
    __syncthreads();
    if (wid == 0) {
        float x = (lane < 8) ? sred[lane] : 0.f;
        x = warpSum(x);
        if (lane == 0) sbc[1] = x;
    }
    __syncthreads();
    float inv = 1.f / sbc[1];
#pragma unroll
    for (int i = 0; i < 8; i++) {
        long long idx = row * S1V + t + i * 256;
        float w = vals[i] * inv;
        weights[idx] = w;
        bf16 h = __float2bfloat16(w);
        wh[idx] = h;
        wl[idx] = __float2bfloat16(w - __bfloat162float(h));
    }
}

// ----------------------------------------------------------------------------
// kernel_launch
// Inputs: value, key, query, mask(int32), W, b.  Output: context | weights.
// ----------------------------------------------------------------------------
extern "C" void kernel_launch(void* const* d_in, const int* in_sizes, int n_in,
                              void* d_out, int out_size)
{
    const float* value = (const float*)d_in[0];
    const float* key   = (const float*)d_in[1];
    const float* query = (const float*)d_in[2];
    const int*   mask  = (const int*)d_in[3];
    const float* W     = (const float*)d_in[4];
    const float* bias  = (const float*)d_in[5];

    float* ctx     = (float*)d_out;                              // [B,S2,H]
    float* weights = (float*)d_out + (size_t)BATCH * S2V * HV;   // [B,S2,S1]

    bf16 *qh, *ql, *kh, *kl, *wh, *wl, *qph, *qpl, *vth, *vtl, *wgh, *wgl;
    float* scores;
    cudaGetSymbolAddress((void**)&qh,  g_qh);   cudaGetSymbolAddress((void**)&ql,  g_ql);
    cudaGetSymbolAddress((void**)&kh,  g_kh);   cudaGetSymbolAddress((void**)&kl,  g_kl);
    cudaGetSymbolAddress((void**)&wh,  g_wh);   cudaGetSymbolAddress((void**)&wl,  g_wl);
    cudaGetSymbolAddress((void**)&qph, g_qph);  cudaGetSymbolAddress((void**)&qpl, g_qpl);
    cudaGetSymbolAddress((void**)&vth, g_vth);  cudaGetSymbolAddress((void**)&vtl, g_vtl);
    cudaGetSymbolAddress((void**)&wgh, g_wgh);  cudaGetSymbolAddress((void**)&wgl, g_wgl);
    cudaGetSymbolAddress((void**)&scores, g_scores);

    cudaFuncSetAttribute(mma_gemm<0,0>, cudaFuncAttributeMaxDynamicSharedMemorySize, SMEM_BYTES);
    cudaFuncSetAttribute(mma_gemm<0,1>, cudaFuncAttributeMaxDynamicSharedMemorySize, SMEM_BYTES);
    cudaFuncSetAttribute(mma_gemm<1,0>, cudaFuncAttributeMaxDynamicSharedMemorySize, SMEM_BYTES);

    // 1) splits / transposes
    split_kernel<<<(BATCH * S1V * HV) / 1024, 256>>>((const float4*)query, (uint32_t*)qh, (uint32_t*)ql);
    split_kernel<<<(BATCH * S2V * HV) / 1024, 256>>>((const float4*)key,   (uint32_t*)kh, (uint32_t*)kl);
    split_kernel<<<(HV * HV) / 1024, 256>>>((const float4*)W, (uint32_t*)wh, (uint32_t*)wl);
    transpose_split_value<<<dim3(HV / 32, S1V / 32, BATCH), dim3(32, 8)>>>(value, vth, vtl);

    // 2) q_proj = query @ W^T + b -> qproj hi/lo   (M=16384, N=1024, K=1024)
    mma_gemm<1,0><<<dim3(HV / TILE_N, (BATCH * S1V) / TILE_M, 1), 256, SMEM_BYTES>>>(
        qh, ql, wh, wl, bias,
        nullptr, qph, qpl, nullptr,
        HV, HV, HV, HV, 0, 0, 0, 0);

    // 3) scoresT[b] = key[b] @ qproj[b]^T with fused mask  (M=S2, N=S1, K=H)
    mma_gemm<0,1><<<dim3(S1V / TILE_N, S2V / TILE_M, BATCH), 256, SMEM_BYTES>>>(
        kh, kl, qph, qpl, nullptr,
        scores, nullptr, nullptr, mask,
        HV, S1V, HV, HV,
        (long long)S2V * HV, (long long)S1V * HV, (long long)S2V * S1V,
        (long long)S1V * S2V);

    // 4) softmax over S1 -> weights (fp32 output) + hi/lo for GEMM3
    softmax_kernel<<<BATCH * S2V, 256>>>(scores, weights, wgh, wgl);

    // 5) context[b] = weights[b] @ valueT[b]^T  (M=S2, N=H, K=S1)
    mma_gemm<0,0><<<dim3(HV / TILE_N, S2V / TILE_M, BATCH), 256, SMEM_BYTES>>>(
        wgh, wgl, vth, vtl, nullptr,
        ctx, nullptr, nullptr, nullptr,
        S1V, HV, S1V, S1V,
        (long long)S2V * S1V, (long long)HV * S1V, (long long)S2V * HV, 0);
}

// round 13
// speedup vs baseline: 1.3766x; 1.0519x over previous
#include <cuda_runtime.h>
#include <cuda_bf16.h>
#include <cstdint>
#include <math.h>

#define BATCH 8
#define S1V   2048
#define S2V   2048
#define HV    1024

typedef __nv_bfloat16 bf16;

// ----------------------------------------------------------------------------
// Scratch (device globals)
// ----------------------------------------------------------------------------
__device__ bf16 g_qh [(size_t)BATCH * S1V * HV];
__device__ bf16 g_ql [(size_t)BATCH * S1V * HV];
__device__ bf16 g_kh [(size_t)BATCH * S2V * HV];
__device__ bf16 g_kl [(size_t)BATCH * S2V * HV];
__device__ bf16 g_wh [(size_t)HV * HV];
__device__ bf16 g_wl [(size_t)HV * HV];
__device__ bf16 g_qph[(size_t)BATCH * S1V * HV];
__device__ bf16 g_qpl[(size_t)BATCH * S1V * HV];
__device__ bf16 g_vth[(size_t)BATCH * HV * S1V];   // valueT [B,H,S1]
__device__ bf16 g_vtl[(size_t)BATCH * HV * S1V];
__device__ bf16 g_wgh[(size_t)BATCH * S2V * S1V];
__device__ bf16 g_wgl[(size_t)BATCH * S2V * S1V];
__device__ float g_scores[(size_t)BATCH * S2V * S1V];  // masked logits [B,S2,S1]

#define NEG_INF __int_as_float(0xff800000)

// ----------------------------------------------------------------------------
// PTX helpers (plain sm_80+ features only)
// ----------------------------------------------------------------------------
__device__ __forceinline__ void cp_async16(uint32_t dst, const void* src) {
    asm volatile("cp.async.cg.shared.global [%0], [%1], 16;" :: "r"(dst), "l"(src));
}
__device__ __forceinline__ uint32_t smem_u32(const void* p) {
    uint32_t a;
    asm("{ .reg .u64 t; cvta.to.shared.u64 t, %1; cvt.u32.u64 %0, t; }" : "=r"(a) : "l"(p));
    return a;
}
#define CP_COMMIT() asm volatile("cp.async.commit_group;" ::: "memory")
#define CP_WAIT0()  asm volatile("cp.async.wait_group 0;" ::: "memory")
#define CP_WAIT1()  asm volatile("cp.async.wait_group 1;" ::: "memory")

__device__ __forceinline__ void ldsm4(uint32_t r[4], uint32_t addr) {
    asm volatile("ldmatrix.sync.aligned.m8n8.x4.shared.b16 {%0,%1,%2,%3}, [%4];"
                 : "=r"(r[0]), "=r"(r[1]), "=r"(r[2]), "=r"(r[3]) : "r"(addr));
}
__device__ __forceinline__ void mma16816(float c[4], const uint32_t a[4],
                                         const uint32_t b0, const uint32_t b1) {
    asm volatile("mma.sync.aligned.m16n8k16.row.col.f32.bf16.bf16.f32 "
                 "{%0,%1,%2,%3}, {%4,%5,%6,%7}, {%8,%9}, {%0,%1,%2,%3};"
                 : "+f"(c[0]), "+f"(c[1]), "+f"(c[2]), "+f"(c[3])
                 : "r"(a[0]), "r"(a[1]), "r"(a[2]), "r"(a[3]), "r"(b0), "r"(b1));
}

#define SWZ(o) ((o) ^ (((o) >> 3) & 0x70))

__device__ __forceinline__ uint32_t pack2(float x0, float x1) {
    bf16 h0 = __float2bfloat16(x0), h1 = __float2bfloat16(x1);
    return (uint32_t)__bfloat16_as_ushort(h0) | ((uint32_t)__bfloat16_as_ushort(h1) << 16);
}

// ----------------------------------------------------------------------------
// Split-bf16 NT GEMM on mma.sync:  C[M,N] = (Ah+Al)[M,K] @ (Bh+Bl)[N,K]^T
// Block tile 128x64, K-chunk 64, SW128 smem, 2-stage cp.async pipeline.
// 8 warps 2(M) x 4(N); warp tile 64x16.  96KB smem + low regs -> 2 CTAs/SM.
// 3 split passes pass-major.  EPI: 0 = fp32 (+ fused mask); 1 = +bias, split.
// ----------------------------------------------------------------------------
#define TILE_M 128
#define TILE_N 64
#define TILE_K 64
#define OFF_AH 0          // 16KB
#define OFF_AL 16384      // 16KB
#define OFF_BH 32768      //  8KB
#define OFF_BL 40960      //  8KB
#define STAGE_BYTES 49152
#define SMEM_BYTES  (2 * STAGE_BYTES)

__device__ __forceinline__ void load_stage(
    uint32_t sbase,
    const bf16* Ah, const bf16* Al, const bf16* Bh, const bf16* Bl,
    long long m0, long long n0, long long ldA, long long ldB, int k0, int tid)
{
#pragma unroll
    for (int i = tid; i < 1024; i += 256) {            // A: 128 rows x 128B
        int r = i >> 3, c = i & 7;
        uint32_t sw = SWZ(r * 128 + c * 16);
        long long goff = (m0 + r) * ldA + k0 + c * 8;
        cp_async16(sbase + OFF_AH + sw, Ah + goff);
        cp_async16(sbase + OFF_AL + sw, Al + goff);
    }
#pragma unroll
    for (int i = tid; i < 512; i += 256) {             // B: 64 rows x 128B
        int r = i >> 3, c = i & 7;
        uint32_t sw = SWZ(r * 128 + c * 16);
        long long goff = (n0 + r) * ldB + k0 + c * 8;
        cp_async16(sbase + OFF_BH + sw, Bh + goff);
        cp_async16(sbase + OFF_BL + sw, Bl + goff);
    }
}

template <int EPI, int MASK>
__global__ __launch_bounds__(256, 2) void mma_gemm(
    const bf16* __restrict__ Ah, const bf16* __restrict__ Al,
    const bf16* __restrict__ Bh, const bf16* __restrict__ Bl,
    const float* __restrict__ bias,
    float* __restrict__ Cf, bf16* __restrict__ Ch, bf16* __restrict__ Cl,
    const int* __restrict__ maskp,
    int K, int N,
    long long ldA, long long ldB,
    long long sA, long long sB, long long sC, long long sMask)
{
    extern __shared__ char smem[];
    const uint32_t sb = smem_u32(smem);

    const int tid  = threadIdx.x;
    const int wid  = tid >> 5;
    const int lane = tid & 31;
    const int wm = wid & 1;      // 2 M-groups of 64
    const int wn = wid >> 1;     // 4 N-groups of 16

    const long long bz = blockIdx.z;
    Ah += bz * sA;  Al += bz * sA;
    Bh += bz * sB;  Bl += bz * sB;
    const int* mb = MASK ? (maskp + bz * sMask) : nullptr;
    const long long m0 = (long long)blockIdx.y * TILE_M;
    const long long n0 = (long long)blockIdx.x * TILE_N;

    // ldmatrix lane addressing (tile index g = lane>>3):
    const int g  = lane >> 3;
    const int lr = lane & 7;
    const int rowA = wm * 64 + (g & 1) * 8 + lr;   // A: m-block = g&1, k-half = g>>1
    const int kbA  = (g >> 1) * 16;
    const int rowB = wn * 16 + (g >> 1) * 8 + lr;  // B: n-block = g>>1, k-half = g&1
    const int kbB  = (g & 1) * 16;

    float acc[4][2][4];
#pragma unroll
    for (int i = 0; i < 4; i++)
#pragma unroll
        for (int j = 0; j < 2; j++)
#pragma unroll
            for (int r = 0; r < 4; r++) acc[i][j][r] = 0.f;

    const int NKC = K / TILE_K;

    load_stage(sb, Ah, Al, Bh, Bl, m0, n0, ldA, ldB, 0, tid);
    CP_COMMIT();

    for (int kc = 0; kc < NKC; ++kc) {
        const uint32_t sbase = sb + (kc & 1) * STAGE_BYTES;
        if (kc + 1 < NKC) {
            load_stage(sb + ((kc + 1) & 1) * STAGE_BYTES,
                       Ah, Al, Bh, Bl, m0, n0, ldA, ldB, (kc + 1) * TILE_K, tid);
            CP_COMMIT();
            CP_WAIT1();
        } else {
            CP_WAIT0();
        }
        __syncthreads();

#pragma unroll
        for (int ks = 0; ks < 4; ++ks) {
            uint32_t ah[4][4], al[4][4];
#pragma unroll
            for (int i = 0; i < 4; i++) {
                uint32_t off = SWZ((uint32_t)((rowA + i * 16) * 128 + ks * 32 + kbA));
                ldsm4(ah[i], sbase + OFF_AH + off);
                ldsm4(al[i], sbase + OFF_AL + off);
            }
            uint32_t bh[4], bl[4];
            {
                uint32_t off = SWZ((uint32_t)(rowB * 128 + ks * 32 + kbB));
                ldsm4(bh, sbase + OFF_BH + off);
                ldsm4(bl, sbase + OFF_BL + off);
            }
            // Pass-major: 8 independent accumulators per pass
#pragma unroll
            for (int i = 0; i < 4; i++)                       // hi * hi
#pragma unroll
                for (int nb = 0; nb < 2; nb++)
                    mma16816(acc[i][nb], ah[i], bh[nb * 2], bh[nb * 2 + 1]);
#pragma unroll
            for (int i = 0; i < 4; i++)                       // hi * lo
#pragma unroll
                for (int nb = 0; nb < 2; nb++)
                    mma16816(acc[i][nb], ah[i], bl[nb * 2], bl[nb * 2 + 1]);
#pragma unroll
            for (int i = 0; i < 4; i++)                       // lo * hi
#pragma unroll
                for (int nb = 0; nb < 2; nb++)
                    mma16816(acc[i][nb], al[i], bh[nb * 2], bh[nb * 2 + 1]);
        }
        __syncthreads();
    }

    // ---- epilogue ----
    const int qr = lane >> 2;          // row within m16
    const int qc = (lane & 3) * 2;     // col within n8
#pragma unroll
    for (int i = 0; i < 4; i++) {
        long long mr0 = m0 + wm * 64 + i * 16 + qr;
#pragma unroll
        for (int j = 0; j < 2; j++) {
            long long n = n0 + wn * 16 + j * 8 + qc;
            float* c = acc[i][j];
            if (EPI == 0) {
                float o0 = c[0], o1 = c[1], o2 = c[2], o3 = c[3];
                if (MASK) {
                    // mask[b][n(s1)][m(s2)], row stride S2V
                    if (mb[n * S2V + mr0])           o0 = NEG_INF;
                    if (mb[(n + 1) * S2V + mr0])     o1 = NEG_INF;
                    if (mb[n * S2V + mr0 + 8])       o2 = NEG_INF;
                    if (mb[(n + 1) * S2V + mr0 + 8]) o3 = NEG_INF;
                }
                *(float2*)(Cf + bz * sC + mr0 * (long long)N + n)       = make_float2(o0, o1);
                *(float2*)(Cf + bz * sC + (mr0 + 8) * (long long)N + n) = make_float2(o2, o3);
            } else {
                float b0 = bias[n], b1 = bias[n + 1];
#pragma unroll
                for (int h = 0; h < 2; h++) {
                    float x0 = c[2 * h]     + b0;
                    float x1 = c[2 * h + 1] + b1;
                    bf16 h0 = __float2bfloat16(x0);
                    bf16 h1 = __float2bfloat16(x1);
                    long long off = (mr0 + 8 * h) * (long long)N + n;
                    *(uint32_t*)(Ch + off) =
                        (uint32_t)__bfloat16_as_ushort(h0) | ((uint32_t)__bfloat16_as_ushort(h1) << 16);
                    *(uint32_t*)(Cl + off) = pack2(x0 - __bfloat162float(h0),
                                                   x1 - __bfloat162float(h1));
                }
            }
        }
    }
}

// ----------------------------------------------------------------------------
// fp32 -> hi/lo bf16 elementwise split
// ----------------------------------------------------------------------------
__global__ __launch_bounds__(256) void split_kernel(
    const float4* __restrict__ in, uint32_t* __restrict__ hi, uint32_t* __restrict__ lo)
{
    long long i = (long long)blockIdx.x * 256 + threadIdx.x;
    float4 v = in[i];
    bf16 h0 = __float2bfloat16(v.x), h1 = __float2bfloat16(v.y);
    bf16 h2 = __float2bfloat16(v.z), h3 = __float2bfloat16(v.w);
    hi[2 * i]     = (uint32_t)__bfloat16_as_ushort(h0) | ((uint32_t)__bfloat16_as_ushort(h1) << 16);
    hi[2 * i + 1] = (uint32_t)__bfloat16_as_ushort(h2) | ((uint32_t)__bfloat16_as_ushort(h3) << 16);
    lo[2 * i]     = pack2(v.x - __bfloat162float(h0), v.y - __bfloat162float(h1));
    lo[2 * i + 1] = pack2(v.z - __bfloat162float(h2), v.w - __bfloat162float(h3));
}

// ----------------------------------------------------------------------------
// value [B,S1,H] fp32 -> valueT hi/lo [B,H,S1] bf16
// ----------------------------------------------------------------------------
__global__ void transpose_split_value(const float* __restrict__ v,
                                      bf16* __restrict__ th, bf16* __restrict__ tl)
{
    __shared__ float tile[32][33];
    int b = blockIdx.z;
    int h0 = blockIdx.x * 32, s0 = blockIdx.y * 32;
    const float* vb = v + (size_t)b * S1V * HV;
    int tx = threadIdx.x, ty = threadIdx.y;
#pragma unroll
    for (int i = 0; i < 32; i += 8)
        tile[ty + i][tx] = vb[(size_t)(s0 + ty + i) * HV + h0 + tx];
    __syncthreads();
    size_t base = (size_t)b * HV * S1V;
#pragma unroll
    for (int i = 0; i < 32; i += 8) {
        float x = tile[tx][ty + i];
        bf16 h = __float2bfloat16(x);
        bf16 l = __float2bfloat16(x - __bfloat162float(h));
        size_t o = base + (size_t)(h0 + ty + i) * S1V + s0 + tx;
        th[o] = h;
        tl[o] = l;
    }
}

// ----------------------------------------------------------------------------
// softmax over S1 (scores pre-masked with -inf in GEMM2 epilogue);
// writes fp32 weights (output) + hi/lo bf16 (for GEMM3)
// ----------------------------------------------------------------------------
__device__ __forceinline__ float warpMax(float v) {
#pragma unroll
    for (int o = 16; o > 0; o >>= 1) v = fmaxf(v, __shfl_xor_sync(0xffffffffu, v, o));
    return v;
}
__device__ __forceinline__ float warpSum(float v) {
#pragma unroll
    for (int o = 16; o > 0; o >>= 1) v += __shfl_xor_sync(0xffffffffu, v, o);
    return v;
}

__global__ __launch_bounds__(256) void softmax_kernel(
    const float* __restrict__ scores,
    float* __restrict__ weights, bf16* __restrict__ wh, bf16* __restrict__ wl)
{
    __shared__ float sred[8];
    __shared__ float sbc[2];

    const long long row = blockIdx.x;
    const float* s = scores + row * S1V;
    const int t = threadIdx.x, lane = t & 31, wid = t >> 5;

    float vals[8];
    float mx = -INFINITY;
#pragma unroll
    for (int i = 0; i < 8; i++) {
        float v = s[t + i * 256];
        vals[i] = v;
        mx = fmaxf(mx, v);
    }
    mx = warpMax(mx);
    if (lane == 0) sred[wid] = mx;
    __syncthreads();
    if (wid == 0) {
        float x = (lane < 8) ? sred[lane] : -INFINITY;
        x = warpMax(x);
        if (lane == 0) sbc[0] = x;
    }
    __syncthreads();
    mx = sbc[0];

    float sum = 0.f;
#pragma unroll
    for (int i = 0; i < 8; i++) { vals[i] = __expf(vals[i] - mx); sum += vals[i]; }
    sum = warpSum(sum);
    if (lane == 0) sred[wid] = sum;
    __syncthreads();
    if (wid == 0) {
        float x = (lane < 8) ? sred[lane] : 0.f;
        x = warpSum(x);
        if (lane == 0) sbc[1] = x;
    }
    __syncthreads();
    float inv = 1.f / sbc[1];
#pragma unroll
    for (int i = 0; i < 8; i++) {
        long long idx = row * S1V + t + i * 256;
        float w = vals[i] * inv;
        weights[idx] = w;
        bf16 h = __float2bfloat16(w);
        wh[idx] = h;
        wl[idx] = __float2bfloat16(w - __bfloat162float(h));
    }
}

// ----------------------------------------------------------------------------
// kernel_launch
// Inputs: value, key, query, mask(int32), W, b.  Output: context | weights.
// ----------------------------------------------------------------------------
extern "C" void kernel_launch(void* const* d_in, const int* in_sizes, int n_in,
                              void* d_out, int out_size)
{
    const float* value = (const float*)d_in[0];
    const float* key   = (const float*)d_in[1];
    const float* query = (const float*)d_in[2];
    const int*   mask  = (const int*)d_in[3];
    const float* W     = (const float*)d_in[4];
    const float* bias  = (const float*)d_in[5];

    float* ctx     = (float*)d_out;                              // [B,S2,H]
    float* weights = (float*)d_out + (size_t)BATCH * S2V * HV;   // [B,S2,S1]

    bf16 *qh, *ql, *kh, *kl, *wh, *wl, *qph, *qpl, *vth, *vtl, *wgh, *wgl;
    float* scores;
    cudaGetSymbolAddress((void**)&qh,  g_qh);   cudaGetSymbolAddress((void**)&ql,  g_ql);
    cudaGetSymbolAddress((void**)&kh,  g_kh);   cudaGetSymbolAddress((void**)&kl,  g_kl);
    cudaGetSymbolAddress((void**)&wh,  g_wh);   cudaGetSymbolAddress((void**)&wl,  g_wl);
    cudaGetSymbolAddress((void**)&qph, g_qph);  cudaGetSymbolAddress((void**)&qpl, g_qpl);
    cudaGetSymbolAddress((void**)&vth, g_vth);  cudaGetSymbolAddress((void**)&vtl, g_vtl);
    cudaGetSymbolAddress((void**)&wgh, g_wgh);  cudaGetSymbolAddress((void**)&wgl, g_wgl);
    cudaGetSymbolAddress((void**)&scores, g_scores);

    cudaFuncSetAttribute(mma_gemm<0,0>, cudaFuncAttributeMaxDynamicSharedMemorySize, SMEM_BYTES);
    cudaFuncSetAttribute(mma_gemm<0,1>, cudaFuncAttributeMaxDynamicSharedMemorySize, SMEM_BYTES);
    cudaFuncSetAttribute(mma_gemm<1,0>, cudaFuncAttributeMaxDynamicSharedMemorySize, SMEM_BYTES);

    // 1) splits / transposes
    split_kernel<<<(BATCH * S1V * HV) / 1024, 256>>>((const float4*)query, (uint32_t*)qh, (uint32_t*)ql);
    split_kernel<<<(BATCH * S2V * HV) / 1024, 256>>>((const float4*)key,   (uint32_t*)kh, (uint32_t*)kl);
    split_kernel<<<(HV * HV) / 1024, 256>>>((const float4*)W, (uint32_t*)wh, (uint32_t*)wl);
    transpose_split_value<<<dim3(HV / 32, S1V / 32, BATCH), dim3(32, 8)>>>(value, vth, vtl);

    // 2) q_proj = query @ W^T + b -> qproj hi/lo   (M=16384, N=1024, K=1024)
    mma_gemm<1,0><<<dim3(HV / TILE_N, (BATCH * S1V) / TILE_M, 1), 256, SMEM_BYTES>>>(
        qh, ql, wh, wl, bias,
        nullptr, qph, qpl, nullptr,
        HV, HV, HV, HV, 0, 0, 0, 0);

    // 3) scoresT[b] = key[b] @ qproj[b]^T with fused mask  (M=S2, N=S1, K=H)
    mma_gemm<0,1><<<dim3(S1V / TILE_N, S2V / TILE_M, BATCH), 256, SMEM_BYTES>>>(
        kh, kl, qph, qpl, nullptr,
        scores, nullptr, nullptr, mask,
        HV, S1V, HV, HV,
        (long long)S2V * HV, (long long)S1V * HV, (long long)S2V * S1V,
        (long long)S1V * S2V);

    // 4) softmax over S1 -> weights (fp32 output) + hi/lo for GEMM3
    softmax_kernel<<<BATCH * S2V, 256>>>(scores, weights, wgh, wgl);

    // 5) context[b] = weights[b] @ valueT[b]^T  (M=S2, N=H, K=S1)
    mma_gemm<0,0><<<dim3(HV / TILE_N, S2V / TILE_M, BATCH), 256, SMEM_BYTES>>>(
        wgh, wgl, vth, vtl, nullptr,
        ctx, nullptr, nullptr, nullptr,
        S1V, HV, S1V, S1V,
        (long long)S2V * S1V, (long long)HV * S1V, (long long)S2V * HV, 0);
}